// round 2
// baseline (speedup 1.0000x reference)
#include <cuda_runtime.h>

// Problem constants (fixed by the dataset)
static constexpr int NN = 50000;   // nodes
static constexpr int NE = 800000;  // edges
// features: 128 -> 128 (hidden) -> 64 (out)

// ---------------- scratch (no allocs allowed -> __device__ globals) ----------
__device__ float g_agg1[(size_t)NN * 128];  // layer1 scatter accumulator
__device__ float g_y2  [(size_t)NN * 64];   // (relu(h1)*nout) @ W2
__device__ float g_agg2[(size_t)NN * 64];   // layer2 scatter accumulator
__device__ int   g_odeg[NN];
__device__ int   g_ideg[NN];
__device__ float g_nout[NN];
__device__ float g_nin [NN];

// ---------------- kernels ----------------------------------------------------

__global__ void zero_all_k() {
    int i0 = blockIdx.x * blockDim.x + threadIdx.x;
    int stride = gridDim.x * blockDim.x;
    const float4 z = make_float4(0.f, 0.f, 0.f, 0.f);
    float4* a1 = reinterpret_cast<float4*>(g_agg1);
    for (int i = i0; i < NN * 128 / 4; i += stride) a1[i] = z;
    float4* a2 = reinterpret_cast<float4*>(g_agg2);
    for (int i = i0; i < NN * 64 / 4; i += stride) a2[i] = z;
    for (int i = i0; i < NN; i += stride) { g_odeg[i] = 0; g_ideg[i] = 0; }
}

__global__ void degree_k(const int* __restrict__ src, const int* __restrict__ dst) {
    int i0 = blockIdx.x * blockDim.x + threadIdx.x;
    int stride = gridDim.x * blockDim.x;
    for (int i = i0; i < NE; i += stride) {
        atomicAdd(&g_odeg[src[i]], 1);
        atomicAdd(&g_ideg[dst[i]], 1);
    }
}

__global__ void norm_k() {
    int i0 = blockIdx.x * blockDim.x + threadIdx.x;
    int stride = gridDim.x * blockDim.x;
    for (int i = i0; i < NN; i += stride) {
        int od = g_odeg[i]; if (od < 1) od = 1;
        int id = g_ideg[i]; if (id < 1) id = 1;
        g_nout[i] = rsqrtf((float)od);
        g_nin[i]  = rsqrtf((float)id);
    }
}

// Layer-1 SpMM: agg1[dst] += h[src] * norm_out[src].  One warp per edge;
// each lane moves one float4 (32 lanes x 16B = 512B row).
__global__ void spmm1_k(const float* __restrict__ h,
                        const int* __restrict__ src, const int* __restrict__ dst) {
    unsigned gw = (blockIdx.x * blockDim.x + threadIdx.x) >> 5;
    if (gw >= NE) return;
    int lane = threadIdx.x & 31;
    int s = src[gw];
    int d = dst[gw];
    float ns = g_nout[s];
    float4 v = reinterpret_cast<const float4*>(h + (size_t)s * 128)[lane];
    v.x *= ns; v.y *= ns; v.z *= ns; v.w *= ns;
    atomicAdd(reinterpret_cast<float4*>(g_agg1 + (size_t)d * 128) + lane, v);
}

// Layer-2 SpMM on pre-multiplied y2 (64 features): agg2[dst] += y2[src].
// One warp per edge; lane moves one float2 (32 x 8B = 256B row).
__global__ void spmm2_k(const int* __restrict__ src, const int* __restrict__ dst) {
    unsigned gw = (blockIdx.x * blockDim.x + threadIdx.x) >> 5;
    if (gw >= NE) return;
    int lane = threadIdx.x & 31;
    int s = src[gw];
    int d = dst[gw];
    float2 v = reinterpret_cast<const float2*>(g_y2 + (size_t)s * 64)[lane];
    atomicAdd(reinterpret_cast<float2*>(g_agg2 + (size_t)d * 64) + lane, v);
}

// Fused double-GEMM per 64-row tile:
//   A  = agg1[rows] * norm_in[row]                       (128 feats, SMEM, transposed)
//   H1 = relu(A @ W1 + b1) * norm_out[row]               (stays in SMEM, transposed)
//   y2[rows] = H1 @ W2                                   (written to GMEM)
// SMEM: W1 64KB + W2 32KB + A^T 32KB + H1^T 32KB + b1 = ~160.5KB -> 1 CTA/SM.
static constexpr int FUSED_SMEM =
    (128 * 128 + 128 * 64 + 128 * 64 + 128 * 64 + 128) * (int)sizeof(float);

__global__ void __launch_bounds__(256, 1)
fused_mlp_k(const float* __restrict__ W1, const float* __restrict__ b1,
            const float* __restrict__ W2) {
    extern __shared__ float sm[];
    float* sW1 = sm;                        // [128][128] row-major (k-major)
    float* sW2 = sm + 16384;                // [128][64]
    float* sA  = sm + 16384 + 8192;         // [128][64]  A^T:  sA[k][m]
    float* sH  = sm + 16384 + 16384;        // [128][64]  H1^T: sH[c][m]
    float* sb  = sm + 16384 + 24576;        // [128]
    const int tid = threadIdx.x;

    // --- stage weights ---
    {
        const float4* w1 = reinterpret_cast<const float4*>(W1);
        float4* d1 = reinterpret_cast<float4*>(sW1);
        #pragma unroll 4
        for (int i = tid; i < 4096; i += 256) d1[i] = w1[i];
        const float4* w2 = reinterpret_cast<const float4*>(W2);
        float4* d2 = reinterpret_cast<float4*>(sW2);
        #pragma unroll 2
        for (int i = tid; i < 2048; i += 256) d2[i] = w2[i];
        if (tid < 128) sb[tid] = b1[tid];
    }

    const int row0 = blockIdx.x * 64;

    // --- stage A tile (scaled by norm_in, transposed into sA[k][m]) ---
    {
        int m = tid >> 2;          // 0..63  local row
        int q = tid & 3;           // k quarter
        int r = row0 + m;
        bool ok = (r < NN);
        float sc = ok ? g_nin[r] : 0.f;
        const float4* ar =
            reinterpret_cast<const float4*>(g_agg1 + (size_t)(ok ? r : 0) * 128);
        #pragma unroll
        for (int kk = 0; kk < 8; kk++) {
            int k4 = q * 8 + kk;                 // float4 index 0..31
            float4 v = ar[k4];
            sA[(k4 * 4 + 0) * 64 + m] = v.x * sc;
            sA[(k4 * 4 + 1) * 64 + m] = v.y * sc;
            sA[(k4 * 4 + 2) * 64 + m] = v.z * sc;
            sA[(k4 * 4 + 3) * 64 + m] = v.w * sc;
        }
    }
    __syncthreads();

    const int tm = tid & 15;   // row group: rows tm*4 .. tm*4+3
    const int tn = tid >> 4;   // col group

    // --- GEMM1: H1(64x128) = A(64x128) @ W1(128x128), 4x8 per thread ---
    {
        float acc[4][8];
        #pragma unroll
        for (int j = 0; j < 4; j++)
            #pragma unroll
            for (int i = 0; i < 8; i++) acc[j][i] = 0.f;

        #pragma unroll 8
        for (int k = 0; k < 128; k++) {
            float4 a  = *reinterpret_cast<const float4*>(sA  + k * 64  + tm * 4);
            float4 bA = *reinterpret_cast<const float4*>(sW1 + k * 128 + tn * 8);
            float4 bB = *reinterpret_cast<const float4*>(sW1 + k * 128 + tn * 8 + 4);
            float av[4] = {a.x, a.y, a.z, a.w};
            float bv[8] = {bA.x, bA.y, bA.z, bA.w, bB.x, bB.y, bB.z, bB.w};
            #pragma unroll
            for (int j = 0; j < 4; j++)
                #pragma unroll
                for (int i = 0; i < 8; i++)
                    acc[j][i] = fmaf(av[j], bv[i], acc[j][i]);
        }

        // epilogue: +b1, relu, *norm_out, store transposed into sH[c][m]
        float no[4];
        #pragma unroll
        for (int j = 0; j < 4; j++) {
            int r = row0 + tm * 4 + j;
            no[j] = (r < NN) ? g_nout[r] : 0.f;
        }
        #pragma unroll
        for (int i = 0; i < 8; i++) {
            int c = tn * 8 + i;
            float bb = sb[c];
            float4 v;
            v.x = fmaxf(acc[0][i] + bb, 0.f) * no[0];
            v.y = fmaxf(acc[1][i] + bb, 0.f) * no[1];
            v.z = fmaxf(acc[2][i] + bb, 0.f) * no[2];
            v.w = fmaxf(acc[3][i] + bb, 0.f) * no[3];
            *reinterpret_cast<float4*>(sH + c * 64 + tm * 4) = v;
        }
    }
    __syncthreads();

    // --- GEMM2: y2(64x64) = H1(64x128) @ W2(128x64), 4x4 per thread ---
    {
        float acc[4][4];
        #pragma unroll
        for (int j = 0; j < 4; j++)
            #pragma unroll
            for (int i = 0; i < 4; i++) acc[j][i] = 0.f;

        #pragma unroll 8
        for (int k = 0; k < 128; k++) {
            float4 a = *reinterpret_cast<const float4*>(sH  + k * 64 + tm * 4);
            float4 b = *reinterpret_cast<const float4*>(sW2 + k * 64 + tn * 4);
            float av[4] = {a.x, a.y, a.z, a.w};
            float bv[4] = {b.x, b.y, b.z, b.w};
            #pragma unroll
            for (int j = 0; j < 4; j++)
                #pragma unroll
                for (int i = 0; i < 4; i++)
                    acc[j][i] = fmaf(av[j], bv[i], acc[j][i]);
        }

        #pragma unroll
        for (int j = 0; j < 4; j++) {
            int r = row0 + tm * 4 + j;
            if (r < NN) {
                float4 o = make_float4(acc[j][0], acc[j][1], acc[j][2], acc[j][3]);
                *reinterpret_cast<float4*>(g_y2 + (size_t)r * 64 + tn * 4) = o;
            }
        }
    }
}

// out = relu(agg2 * norm_in[row] + b2[col])
__global__ void final_k(const float* __restrict__ b2, float* __restrict__ out) {
    int i0 = blockIdx.x * blockDim.x + threadIdx.x;
    int stride = gridDim.x * blockDim.x;
    for (int i = i0; i < NN * 64; i += stride) {
        int r = i >> 6;
        int c = i & 63;
        out[i] = fmaxf(fmaf(g_agg2[i], g_nin[r], b2[c]), 0.f);
    }
}

// ---------------- launch ------------------------------------------------------

extern "C" void kernel_launch(void* const* d_in, const int* in_sizes, int n_in,
                              void* d_out, int out_size) {
    const float* h  = (const float*)d_in[0];
    const float* W1 = (const float*)d_in[1];
    const float* b1 = (const float*)d_in[2];
    const float* W2 = (const float*)d_in[3];
    const float* b2 = (const float*)d_in[4];
    const int*   src = (const int*)d_in[5];   // jax int64 canonicalizes to int32
    const int*   dst = (const int*)d_in[6];
    float* out = (float*)d_out;
    (void)in_sizes; (void)n_in; (void)out_size;

    cudaFuncSetAttribute(fused_mlp_k,
                         cudaFuncAttributeMaxDynamicSharedMemorySize, FUSED_SMEM);

    zero_all_k<<<1024, 256>>>();
    degree_k<<<2048, 256>>>(src, dst);
    norm_k<<<196, 256>>>();
    spmm1_k<<<NE / 8, 256>>>(h, src, dst);                    // 1 warp/edge
    fused_mlp_k<<<(NN + 63) / 64, 256, FUSED_SMEM>>>(W1, b1, W2);
    spmm2_k<<<NE / 8, 256>>>(src, dst);                       // 1 warp/edge
    final_k<<<2048, 256>>>(b2, out);
}

// round 3
// speedup vs baseline: 1.0578x; 1.0578x over previous
#include <cuda_runtime.h>

// Problem constants (fixed by the dataset)
static constexpr int NN = 50000;   // nodes
static constexpr int NE = 800000;  // edges
// features: 128 -> 128 (hidden) -> 64 (out)

// ---------------- scratch (__device__ globals; no allocs allowed) ------------
__device__ float g_ax [(size_t)NN * 128];  // nin-scaled layer1 aggregate (GEMM input A)
__device__ float g_y2 [(size_t)NN * 64];   // (relu(h1)*nout) @ W2
__device__ int   g_odeg[NN];
__device__ int   g_ideg[NN];
__device__ float g_nout[NN];
__device__ float g_nin [NN];
__device__ int   g_off [NN + 1];           // CSR offsets (by dst)
__device__ int   g_cur [NN];               // scatter cursors
__device__ int   g_bucket[NE];             // src ids grouped by dst

// ---------------- graph preprocessing ----------------------------------------

__global__ void zero_deg_k() {
    int i0 = blockIdx.x * blockDim.x + threadIdx.x;
    int stride = gridDim.x * blockDim.x;
    for (int i = i0; i < NN; i += stride) { g_odeg[i] = 0; g_ideg[i] = 0; }
}

__global__ void degree_k(const int* __restrict__ src, const int* __restrict__ dst) {
    int i0 = blockIdx.x * blockDim.x + threadIdx.x;
    int stride = gridDim.x * blockDim.x;
    for (int i = i0; i < NE; i += stride) {
        atomicAdd(&g_odeg[src[i]], 1);
        atomicAdd(&g_ideg[dst[i]], 1);
    }
}

__global__ void norm_k() {
    int i0 = blockIdx.x * blockDim.x + threadIdx.x;
    int stride = gridDim.x * blockDim.x;
    for (int i = i0; i < NN; i += stride) {
        int od = g_odeg[i]; if (od < 1) od = 1;
        int id = g_ideg[i]; if (id < 1) id = 1;
        g_nout[i] = rsqrtf((float)od);
        g_nin[i]  = rsqrtf((float)id);
    }
}

// Single-block exclusive prefix scan of g_ideg -> g_off (and g_cur copy).
__global__ void __launch_bounds__(1024, 1) scan_k() {
    __shared__ int part[1024];
    const int T = 1024;
    const int chunk = (NN + T - 1) / T;   // 49
    int t = threadIdx.x;
    int begin = t * chunk;
    int endi  = begin + chunk; if (endi > NN) endi = NN;

    int sum = 0;
    for (int i = begin; i < endi; i++) sum += g_ideg[i];
    part[t] = sum;
    __syncthreads();

    // Hillis-Steele inclusive scan over block partials
    for (int d = 1; d < T; d <<= 1) {
        int v = (t >= d) ? part[t - d] : 0;
        __syncthreads();
        part[t] += v;
        __syncthreads();
    }
    int running = (t == 0) ? 0 : part[t - 1];   // exclusive prefix of my chunk
    for (int i = begin; i < endi; i++) {
        g_off[i] = running;
        g_cur[i] = running;
        running += g_ideg[i];
    }
    if (t == T - 1) g_off[NN] = NE;
}

__global__ void scatter_k(const int* __restrict__ src, const int* __restrict__ dst) {
    int i0 = blockIdx.x * blockDim.x + threadIdx.x;
    int stride = gridDim.x * blockDim.x;
    for (int i = i0; i < NE; i += stride) {
        int d = dst[i];
        int pos = atomicAdd(&g_cur[d], 1);
        g_bucket[pos] = src[i];
    }
}

// ---------------- layer-1 SpMM as gather --------------------------------------
// One warp per dst node; lanes hold 4 feats each (128 total).
// g_ax[n] = nin[n] * sum_{e in in(n)} h[src_e] * nout[src_e]
__global__ void spmm1g_k(const float* __restrict__ h) {
    unsigned w = (blockIdx.x * blockDim.x + threadIdx.x) >> 5;
    if (w >= NN) return;
    int lane = threadIdx.x & 31;
    int beg = g_off[w];
    int end = g_off[w + 1];
    const float4* h4 = reinterpret_cast<const float4*>(h);

    float4 acc = make_float4(0.f, 0.f, 0.f, 0.f);
    int e = beg;
    for (; e + 1 < end; e += 2) {
        int s0 = __ldg(&g_bucket[e]);
        int s1 = __ldg(&g_bucket[e + 1]);
        float n0 = g_nout[s0];
        float n1 = g_nout[s1];
        float4 v0 = h4[(size_t)s0 * 32 + lane];
        float4 v1 = h4[(size_t)s1 * 32 + lane];
        acc.x = fmaf(v0.x, n0, acc.x); acc.y = fmaf(v0.y, n0, acc.y);
        acc.z = fmaf(v0.z, n0, acc.z); acc.w = fmaf(v0.w, n0, acc.w);
        acc.x = fmaf(v1.x, n1, acc.x); acc.y = fmaf(v1.y, n1, acc.y);
        acc.z = fmaf(v1.z, n1, acc.z); acc.w = fmaf(v1.w, n1, acc.w);
    }
    if (e < end) {
        int s0 = __ldg(&g_bucket[e]);
        float n0 = g_nout[s0];
        float4 v0 = h4[(size_t)s0 * 32 + lane];
        acc.x = fmaf(v0.x, n0, acc.x); acc.y = fmaf(v0.y, n0, acc.y);
        acc.z = fmaf(v0.z, n0, acc.z); acc.w = fmaf(v0.w, n0, acc.w);
    }
    float ni = g_nin[w];
    acc.x *= ni; acc.y *= ni; acc.z *= ni; acc.w *= ni;
    reinterpret_cast<float4*>(g_ax)[(size_t)w * 32 + lane] = acc;
}

// ---------------- layer-2 SpMM as gather + fused epilogue ---------------------
// One warp per dst node; lanes hold 2 feats each (64 total).
// out[n] = relu( nin[n] * sum_{e in in(n)} y2[src_e] + b2 )
__global__ void spmm2g_k(const float* __restrict__ b2, float* __restrict__ out) {
    unsigned w = (blockIdx.x * blockDim.x + threadIdx.x) >> 5;
    if (w >= NN) return;
    int lane = threadIdx.x & 31;
    int beg = g_off[w];
    int end = g_off[w + 1];
    const float2* y2 = reinterpret_cast<const float2*>(g_y2);

    float2 acc = make_float2(0.f, 0.f);
    int e = beg;
    for (; e + 1 < end; e += 2) {
        int s0 = __ldg(&g_bucket[e]);
        int s1 = __ldg(&g_bucket[e + 1]);
        float2 v0 = y2[(size_t)s0 * 32 + lane];
        float2 v1 = y2[(size_t)s1 * 32 + lane];
        acc.x += v0.x + v1.x;
        acc.y += v0.y + v1.y;
    }
    if (e < end) {
        int s0 = __ldg(&g_bucket[e]);
        float2 v0 = y2[(size_t)s0 * 32 + lane];
        acc.x += v0.x;
        acc.y += v0.y;
    }
    float ni = g_nin[w];
    float2 bb = reinterpret_cast<const float2*>(b2)[lane];
    float2 o;
    o.x = fmaxf(fmaf(acc.x, ni, bb.x), 0.f);
    o.y = fmaxf(fmaf(acc.y, ni, bb.y), 0.f);
    reinterpret_cast<float2*>(out)[(size_t)w * 32 + lane] = o;
}

// ---------------- fused double-GEMM -------------------------------------------
// Per 64-row tile:
//   A  = g_ax[rows]                         (already nin-scaled, SMEM, transposed)
//   H1 = relu(A @ W1 + b1) * norm_out[row]  (stays in SMEM, transposed)
//   y2[rows] = H1 @ W2
static constexpr int FUSED_SMEM =
    (128 * 128 + 128 * 64 + 128 * 64 + 128 * 64 + 128) * (int)sizeof(float);

__global__ void __launch_bounds__(256, 1)
fused_mlp_k(const float* __restrict__ W1, const float* __restrict__ b1,
            const float* __restrict__ W2) {
    extern __shared__ float sm[];
    float* sW1 = sm;                        // [128][128] k-major
    float* sW2 = sm + 16384;                // [128][64]
    float* sA  = sm + 16384 + 8192;         // [128][64]  A^T:  sA[k][m]
    float* sH  = sm + 16384 + 16384;        // [128][64]  H1^T: sH[c][m]
    float* sb  = sm + 16384 + 24576;        // [128]
    const int tid = threadIdx.x;

    // stage weights
    {
        const float4* w1 = reinterpret_cast<const float4*>(W1);
        float4* d1 = reinterpret_cast<float4*>(sW1);
        #pragma unroll 4
        for (int i = tid; i < 4096; i += 256) d1[i] = w1[i];
        const float4* w2 = reinterpret_cast<const float4*>(W2);
        float4* d2 = reinterpret_cast<float4*>(sW2);
        #pragma unroll 2
        for (int i = tid; i < 2048; i += 256) d2[i] = w2[i];
        if (tid < 128) sb[tid] = b1[tid];
    }

    const int row0 = blockIdx.x * 64;

    // stage A tile (transposed into sA[k][m]); rows >= NN are zero
    {
        int m = tid >> 2;          // 0..63
        int q = tid & 3;
        int r = row0 + m;
        bool ok = (r < NN);
        const float4* ar =
            reinterpret_cast<const float4*>(g_ax + (size_t)(ok ? r : 0) * 128);
        #pragma unroll
        for (int kk = 0; kk < 8; kk++) {
            int k4 = q * 8 + kk;
            float4 v = ok ? ar[k4] : make_float4(0.f, 0.f, 0.f, 0.f);
            sA[(k4 * 4 + 0) * 64 + m] = v.x;
            sA[(k4 * 4 + 1) * 64 + m] = v.y;
            sA[(k4 * 4 + 2) * 64 + m] = v.z;
            sA[(k4 * 4 + 3) * 64 + m] = v.w;
        }
    }
    __syncthreads();

    const int tm = tid & 15;   // row group (rows tm*4..tm*4+3)
    const int tn = tid >> 4;   // col group

    // GEMM1: H1(64x128) = A @ W1, 4x8 per thread
    {
        float acc[4][8];
        #pragma unroll
        for (int j = 0; j < 4; j++)
            #pragma unroll
            for (int i = 0; i < 8; i++) acc[j][i] = 0.f;

        #pragma unroll 8
        for (int k = 0; k < 128; k++) {
            float4 a  = *reinterpret_cast<const float4*>(sA  + k * 64  + tm * 4);
            float4 bA = *reinterpret_cast<const float4*>(sW1 + k * 128 + tn * 8);
            float4 bB = *reinterpret_cast<const float4*>(sW1 + k * 128 + tn * 8 + 4);
            float av[4] = {a.x, a.y, a.z, a.w};
            float bv[8] = {bA.x, bA.y, bA.z, bA.w, bB.x, bB.y, bB.z, bB.w};
            #pragma unroll
            for (int j = 0; j < 4; j++)
                #pragma unroll
                for (int i = 0; i < 8; i++)
                    acc[j][i] = fmaf(av[j], bv[i], acc[j][i]);
        }

        float no[4];
        #pragma unroll
        for (int j = 0; j < 4; j++) {
            int r = row0 + tm * 4 + j;
            no[j] = (r < NN) ? g_nout[r] : 0.f;
        }
        #pragma unroll
        for (int i = 0; i < 8; i++) {
            int c = tn * 8 + i;
            float bb = sb[c];
            float4 v;
            v.x = fmaxf(acc[0][i] + bb, 0.f) * no[0];
            v.y = fmaxf(acc[1][i] + bb, 0.f) * no[1];
            v.z = fmaxf(acc[2][i] + bb, 0.f) * no[2];
            v.w = fmaxf(acc[3][i] + bb, 0.f) * no[3];
            *reinterpret_cast<float4*>(sH + c * 64 + tm * 4) = v;
        }
    }
    __syncthreads();

    // GEMM2: y2(64x64) = H1 @ W2, 4x4 per thread
    {
        float acc[4][4];
        #pragma unroll
        for (int j = 0; j < 4; j++)
            #pragma unroll
            for (int i = 0; i < 4; i++) acc[j][i] = 0.f;

        #pragma unroll 8
        for (int k = 0; k < 128; k++) {
            float4 a = *reinterpret_cast<const float4*>(sH  + k * 64 + tm * 4);
            float4 b = *reinterpret_cast<const float4*>(sW2 + k * 64 + tn * 4);
            float av[4] = {a.x, a.y, a.z, a.w};
            float bv[4] = {b.x, b.y, b.z, b.w};
            #pragma unroll
            for (int j = 0; j < 4; j++)
                #pragma unroll
                for (int i = 0; i < 4; i++)
                    acc[j][i] = fmaf(av[j], bv[i], acc[j][i]);
        }

        #pragma unroll
        for (int j = 0; j < 4; j++) {
            int r = row0 + tm * 4 + j;
            if (r < NN) {
                float4 o = make_float4(acc[j][0], acc[j][1], acc[j][2], acc[j][3]);
                *reinterpret_cast<float4*>(g_y2 + (size_t)r * 64 + tn * 4) = o;
            }
        }
    }
}

// ---------------- launch ------------------------------------------------------

extern "C" void kernel_launch(void* const* d_in, const int* in_sizes, int n_in,
                              void* d_out, int out_size) {
    const float* h  = (const float*)d_in[0];
    const float* W1 = (const float*)d_in[1];
    const float* b1 = (const float*)d_in[2];
    const float* W2 = (const float*)d_in[3];
    const float* b2 = (const float*)d_in[4];
    const int*   src = (const int*)d_in[5];
    const int*   dst = (const int*)d_in[6];
    float* out = (float*)d_out;
    (void)in_sizes; (void)n_in; (void)out_size;

    cudaFuncSetAttribute(fused_mlp_k,
                         cudaFuncAttributeMaxDynamicSharedMemorySize, FUSED_SMEM);

    zero_deg_k<<<98, 512>>>();
    degree_k<<<1024, 256>>>(src, dst);
    norm_k<<<98, 512>>>();
    scan_k<<<1, 1024>>>();
    scatter_k<<<1024, 256>>>(src, dst);
    spmm1g_k<<<(NN * 32 + 255) / 256, 256>>>(h);          // 1 warp/node
    fused_mlp_k<<<(NN + 63) / 64, 256, FUSED_SMEM>>>(W1, b1, W2);
    spmm2g_k<<<(NN * 32 + 255) / 256, 256>>>(b2, out);    // 1 warp/node
}

// round 5
// speedup vs baseline: 1.4318x; 1.3536x over previous
#include <cuda_runtime.h>

// Problem constants (fixed by the dataset)
static constexpr int NN = 50000;   // nodes
static constexpr int NE = 800000;  // edges
// features: 128 -> 128 (hidden) -> 64 (out)

// scan decomposition
static constexpr int SCAN_T = 1024;                    // total scan threads
static constexpr int CHUNK  = (NN + SCAN_T - 1) / SCAN_T;  // 49

// ---------------- scratch (__device__ globals; no allocs allowed) ------------
__device__ float g_ax [(size_t)NN * 128];  // nin-scaled layer1 aggregate (GEMM input A)
__device__ float g_y2 [(size_t)NN * 64];   // (relu(h1)*nout) @ W2
__device__ int   g_odeg[NN];
__device__ int   g_ideg[NN];
__device__ float g_nout[NN];
__device__ float g_nin [NN];
__device__ int   g_off [NN + 1];           // CSR offsets (by dst)
__device__ int   g_cur [NN];               // scatter cursors
__device__ int   g_bucket[NE];             // src ids grouped by dst
__device__ int   g_part[SCAN_T];           // per-chunk partial sums
__device__ int   g_pref[SCAN_T];           // exclusive prefix of partials

// ---------------- graph preprocessing ----------------------------------------

__global__ void zero_deg_k() {
    int i0 = blockIdx.x * blockDim.x + threadIdx.x;
    int stride = gridDim.x * blockDim.x;
    for (int i = i0; i < NN; i += stride) { g_odeg[i] = 0; g_ideg[i] = 0; }
}

__global__ void degree_k(const int* __restrict__ src, const int* __restrict__ dst) {
    int i0 = blockIdx.x * blockDim.x + threadIdx.x;
    int stride = gridDim.x * blockDim.x;
    for (int i = i0; i < NE; i += stride) {
        atomicAdd(&g_odeg[src[i]], 1);
        atomicAdd(&g_ideg[dst[i]], 1);
    }
}

__global__ void norm_k() {
    int i0 = blockIdx.x * blockDim.x + threadIdx.x;
    int stride = gridDim.x * blockDim.x;
    for (int i = i0; i < NN; i += stride) {
        int od = g_odeg[i]; if (od < 1) od = 1;
        int id = g_ideg[i]; if (id < 1) id = 1;
        g_nout[i] = rsqrtf((float)od);
        g_nin[i]  = rsqrtf((float)id);
    }
}

// ---- 3-phase chip-wide exclusive scan of g_ideg -> g_off / g_cur -------------

// Phase A: per-chunk partial sums (parallel across 1024 threads / 8 CTAs).
__global__ void partial_k() {
    int t = blockIdx.x * blockDim.x + threadIdx.x;   // 0..1023
    if (t >= SCAN_T) return;
    int begin = t * CHUNK;
    int endi  = begin + CHUNK; if (endi > NN) endi = NN;
    int sum = 0;
    #pragma unroll 7
    for (int i = begin; i < endi; i++) sum += g_ideg[i];
    g_part[t] = sum;
}

// Phase B: scan the 1024 partials in a single block (SMEM only).
__global__ void __launch_bounds__(SCAN_T, 1) scanpart_k() {
    __shared__ int part[SCAN_T];
    int t = threadIdx.x;
    part[t] = g_part[t];
    __syncthreads();
    for (int d = 1; d < SCAN_T; d <<= 1) {
        int v = (t >= d) ? part[t - d] : 0;
        __syncthreads();
        part[t] += v;
        __syncthreads();
    }
    g_pref[t] = (t == 0) ? 0 : part[t - 1];   // exclusive
}

// Phase C: each thread replays its chunk writing offsets (parallel).
__global__ void offsets_k() {
    int t = blockIdx.x * blockDim.x + threadIdx.x;
    if (t >= SCAN_T) return;
    int begin = t * CHUNK;
    int endi  = begin + CHUNK; if (endi > NN) endi = NN;
    int running = g_pref[t];
    #pragma unroll 7
    for (int i = begin; i < endi; i++) {
        g_off[i] = running;
        g_cur[i] = running;
        running += g_ideg[i];
    }
    if (t == SCAN_T - 1) g_off[NN] = NE;
}

__global__ void scatter_k(const int* __restrict__ src, const int* __restrict__ dst) {
    int i0 = blockIdx.x * blockDim.x + threadIdx.x;
    int stride = gridDim.x * blockDim.x;
    for (int i = i0; i < NE; i += stride) {
        int d = dst[i];
        int pos = atomicAdd(&g_cur[d], 1);
        g_bucket[pos] = src[i];
    }
}

// ---------------- layer-1 SpMM as gather --------------------------------------
// One warp per dst node; lanes hold 4 feats each (128 total).
// g_ax[n] = nin[n] * sum_{e in in(n)} h[src_e] * nout[src_e]
__global__ void spmm1g_k(const float* __restrict__ h) {
    unsigned w = (blockIdx.x * blockDim.x + threadIdx.x) >> 5;
    if (w >= NN) return;
    int lane = threadIdx.x & 31;
    int beg = g_off[w];
    int end = g_off[w + 1];
    const float4* h4 = reinterpret_cast<const float4*>(h);

    float4 acc = make_float4(0.f, 0.f, 0.f, 0.f);
    int e = beg;
    for (; e + 1 < end; e += 2) {
        int s0 = __ldg(&g_bucket[e]);
        int s1 = __ldg(&g_bucket[e + 1]);
        float n0 = g_nout[s0];
        float n1 = g_nout[s1];
        float4 v0 = h4[(size_t)s0 * 32 + lane];
        float4 v1 = h4[(size_t)s1 * 32 + lane];
        acc.x = fmaf(v0.x, n0, acc.x); acc.y = fmaf(v0.y, n0, acc.y);
        acc.z = fmaf(v0.z, n0, acc.z); acc.w = fmaf(v0.w, n0, acc.w);
        acc.x = fmaf(v1.x, n1, acc.x); acc.y = fmaf(v1.y, n1, acc.y);
        acc.z = fmaf(v1.z, n1, acc.z); acc.w = fmaf(v1.w, n1, acc.w);
    }
    if (e < end) {
        int s0 = __ldg(&g_bucket[e]);
        float n0 = g_nout[s0];
        float4 v0 = h4[(size_t)s0 * 32 + lane];
        acc.x = fmaf(v0.x, n0, acc.x); acc.y = fmaf(v0.y, n0, acc.y);
        acc.z = fmaf(v0.z, n0, acc.z); acc.w = fmaf(v0.w, n0, acc.w);
    }
    float ni = g_nin[w];
    acc.x *= ni; acc.y *= ni; acc.z *= ni; acc.w *= ni;
    reinterpret_cast<float4*>(g_ax)[(size_t)w * 32 + lane] = acc;
}

// ---------------- layer-2 SpMM as gather + fused epilogue ---------------------
// One warp per dst node; lanes hold 2 feats each (64 total).
// out[n] = relu( nin[n] * sum_{e in in(n)} y2[src_e] + b2 )
__global__ void spmm2g_k(const float* __restrict__ b2, float* __restrict__ out) {
    unsigned w = (blockIdx.x * blockDim.x + threadIdx.x) >> 5;
    if (w >= NN) return;
    int lane = threadIdx.x & 31;
    int beg = g_off[w];
    int end = g_off[w + 1];
    const float2* y2 = reinterpret_cast<const float2*>(g_y2);

    float2 acc = make_float2(0.f, 0.f);
    int e = beg;
    for (; e + 1 < end; e += 2) {
        int s0 = __ldg(&g_bucket[e]);
        int s1 = __ldg(&g_bucket[e + 1]);
        float2 v0 = y2[(size_t)s0 * 32 + lane];
        float2 v1 = y2[(size_t)s1 * 32 + lane];
        acc.x += v0.x + v1.x;
        acc.y += v0.y + v1.y;
    }
    if (e < end) {
        int s0 = __ldg(&g_bucket[e]);
        float2 v0 = y2[(size_t)s0 * 32 + lane];
        acc.x += v0.x;
        acc.y += v0.y;
    }
    float ni = g_nin[w];
    float2 bb = reinterpret_cast<const float2*>(b2)[lane];
    float2 o;
    o.x = fmaxf(fmaf(acc.x, ni, bb.x), 0.f);
    o.y = fmaxf(fmaf(acc.y, ni, bb.y), 0.f);
    reinterpret_cast<float2*>(out)[(size_t)w * 32 + lane] = o;
}

// ---------------- fused double-GEMM -------------------------------------------
// Per 64-row tile:
//   A  = g_ax[rows]                         (already nin-scaled, SMEM, transposed)
//   H1 = relu(A @ W1 + b1) * norm_out[row]  (stays in SMEM, transposed)
//   y2[rows] = H1 @ W2
static constexpr int FUSED_SMEM =
    (128 * 128 + 128 * 64 + 128 * 64 + 128 * 64 + 128) * (int)sizeof(float);

__global__ void __launch_bounds__(256, 1)
fused_mlp_k(const float* __restrict__ W1, const float* __restrict__ b1,
            const float* __restrict__ W2) {
    extern __shared__ float sm[];
    float* sW1 = sm;                        // [128][128] k-major
    float* sW2 = sm + 16384;                // [128][64]
    float* sA  = sm + 16384 + 8192;         // [128][64]  A^T:  sA[k][m]
    float* sH  = sm + 16384 + 16384;        // [128][64]  H1^T: sH[c][m]
    float* sb  = sm + 16384 + 24576;        // [128]
    const int tid = threadIdx.x;

    // stage weights
    {
        const float4* w1 = reinterpret_cast<const float4*>(W1);
        float4* d1 = reinterpret_cast<float4*>(sW1);
        #pragma unroll 4
        for (int i = tid; i < 4096; i += 256) d1[i] = w1[i];
        const float4* w2 = reinterpret_cast<const float4*>(W2);
        float4* d2 = reinterpret_cast<float4*>(sW2);
        #pragma unroll 2
        for (int i = tid; i < 2048; i += 256) d2[i] = w2[i];
        if (tid < 128) sb[tid] = b1[tid];
    }

    const int row0 = blockIdx.x * 64;

    // stage A tile (transposed into sA[k][m]); rows >= NN are zero
    {
        int m = tid >> 2;          // 0..63
        int q = tid & 3;
        int r = row0 + m;
        bool ok = (r < NN);
        const float4* ar =
            reinterpret_cast<const float4*>(g_ax + (size_t)(ok ? r : 0) * 128);
        #pragma unroll
        for (int kk = 0; kk < 8; kk++) {
            int k4 = q * 8 + kk;
            float4 v = ok ? ar[k4] : make_float4(0.f, 0.f, 0.f, 0.f);
            sA[(k4 * 4 + 0) * 64 + m] = v.x;
            sA[(k4 * 4 + 1) * 64 + m] = v.y;
            sA[(k4 * 4 + 2) * 64 + m] = v.z;
            sA[(k4 * 4 + 3) * 64 + m] = v.w;
        }
    }
    __syncthreads();

    const int tm = tid & 15;   // row group (rows tm*4..tm*4+3)
    const int tn = tid >> 4;   // col group

    // GEMM1: H1(64x128) = A @ W1, 4x8 per thread
    {
        float acc[4][8];
        #pragma unroll
        for (int j = 0; j < 4; j++)
            #pragma unroll
            for (int i = 0; i < 8; i++) acc[j][i] = 0.f;

        #pragma unroll 8
        for (int k = 0; k < 128; k++) {
            float4 a  = *reinterpret_cast<const float4*>(sA  + k * 64  + tm * 4);
            float4 bA = *reinterpret_cast<const float4*>(sW1 + k * 128 + tn * 8);
            float4 bB = *reinterpret_cast<const float4*>(sW1 + k * 128 + tn * 8 + 4);
            float av[4] = {a.x, a.y, a.z, a.w};
            float bv[8] = {bA.x, bA.y, bA.z, bA.w, bB.x, bB.y, bB.z, bB.w};
            #pragma unroll
            for (int j = 0; j < 4; j++)
                #pragma unroll
                for (int i = 0; i < 8; i++)
                    acc[j][i] = fmaf(av[j], bv[i], acc[j][i]);
        }

        float no[4];
        #pragma unroll
        for (int j = 0; j < 4; j++) {
            int r = row0 + tm * 4 + j;
            no[j] = (r < NN) ? g_nout[r] : 0.f;
        }
        #pragma unroll
        for (int i = 0; i < 8; i++) {
            int c = tn * 8 + i;
            float bb = sb[c];
            float4 v;
            v.x = fmaxf(acc[0][i] + bb, 0.f) * no[0];
            v.y = fmaxf(acc[1][i] + bb, 0.f) * no[1];
            v.z = fmaxf(acc[2][i] + bb, 0.f) * no[2];
            v.w = fmaxf(acc[3][i] + bb, 0.f) * no[3];
            *reinterpret_cast<float4*>(sH + c * 64 + tm * 4) = v;
        }
    }
    __syncthreads();

    // GEMM2: y2(64x64) = H1 @ W2, 4x4 per thread
    {
        float acc[4][4];
        #pragma unroll
        for (int j = 0; j < 4; j++)
            #pragma unroll
            for (int i = 0; i < 4; i++) acc[j][i] = 0.f;

        #pragma unroll 8
        for (int k = 0; k < 128; k++) {
            float4 a = *reinterpret_cast<const float4*>(sH  + k * 64 + tm * 4);
            float4 b = *reinterpret_cast<const float4*>(sW2 + k * 64 + tn * 4);
            float av[4] = {a.x, a.y, a.z, a.w};
            float bv[4] = {b.x, b.y, b.z, b.w};
            #pragma unroll
            for (int j = 0; j < 4; j++)
                #pragma unroll
                for (int i = 0; i < 4; i++)
                    acc[j][i] = fmaf(av[j], bv[i], acc[j][i]);
        }

        #pragma unroll
        for (int j = 0; j < 4; j++) {
            int r = row0 + tm * 4 + j;
            if (r < NN) {
                float4 o = make_float4(acc[j][0], acc[j][1], acc[j][2], acc[j][3]);
                *reinterpret_cast<float4*>(g_y2 + (size_t)r * 64 + tn * 4) = o;
            }
        }
    }
}

// ---------------- launch ------------------------------------------------------

extern "C" void kernel_launch(void* const* d_in, const int* in_sizes, int n_in,
                              void* d_out, int out_size) {
    const float* h  = (const float*)d_in[0];
    const float* W1 = (const float*)d_in[1];
    const float* b1 = (const float*)d_in[2];
    const float* W2 = (const float*)d_in[3];
    const float* b2 = (const float*)d_in[4];
    const int*   src = (const int*)d_in[5];
    const int*   dst = (const int*)d_in[6];
    float* out = (float*)d_out;
    (void)in_sizes; (void)n_in; (void)out_size;

    cudaFuncSetAttribute(fused_mlp_k,
                         cudaFuncAttributeMaxDynamicSharedMemorySize, FUSED_SMEM);

    zero_deg_k<<<98, 512>>>();
    degree_k<<<1024, 256>>>(src, dst);
    norm_k<<<98, 512>>>();
    partial_k<<<8, 128>>>();          // 3-phase parallel scan
    scanpart_k<<<1, SCAN_T>>>();
    offsets_k<<<8, 128>>>();
    scatter_k<<<1024, 256>>>(src, dst);
    spmm1g_k<<<(NN * 32 + 255) / 256, 256>>>(h);          // 1 warp/node
    fused_mlp_k<<<(NN + 63) / 64, 256, FUSED_SMEM>>>(W1, b1, W2);
    spmm2g_k<<<(NN * 32 + 255) / 256, 256>>>(b2, out);    // 1 warp/node
}

// round 7
// speedup vs baseline: 1.4641x; 1.0225x over previous
#include <cuda_runtime.h>

// Problem constants (fixed by the dataset)
static constexpr int NN = 50000;   // nodes
static constexpr int NE = 800000;  // edges
// features: 128 -> 128 (hidden) -> 64 (out)

// scan decomposition (CHUNK divisible by 4 for int4 loads; NN%4==0)
static constexpr int SCAN_T = 1024;
static constexpr int CHUNK  = 52;          // 1024*52 = 53248 >= NN

// ---------------- scratch (__device__ globals; no allocs allowed) ------------
__device__ float g_ax [(size_t)NN * 128];  // nin-scaled layer1 aggregate (GEMM input A)
__device__ float g_y2 [(size_t)NN * 64];   // (relu(h1)*nout) @ W2
__device__ int   g_odeg[NN];
__device__ int   g_ideg[NN];
__device__ float g_nout[NN];
__device__ float g_nin [NN];
__device__ int   g_off [NN + 1];           // CSR offsets (by dst)
__device__ int   g_cur [NN];               // scatter cursors
__device__ int   g_bucket[NE];             // src ids grouped by dst
__device__ int   g_part[SCAN_T];           // per-chunk partial sums
__device__ int   g_pref[SCAN_T];           // exclusive prefix of partials

// ---------------- packed f32x2 helpers (PTX-only; ptxas won't auto-fuse) -----
__device__ __forceinline__ void fma2(unsigned long long& d,
                                     unsigned long long a,
                                     unsigned long long b) {
    asm("fma.rn.f32x2 %0, %1, %2, %0;" : "+l"(d) : "l"(a), "l"(b));
}
__device__ __forceinline__ unsigned long long pack2(float x) {
    unsigned long long r;
    asm("mov.b64 %0, {%1, %1};" : "=l"(r) : "f"(x));
    return r;
}
__device__ __forceinline__ float2 unpk(unsigned long long v) {
    float lo, hi;
    asm("mov.b64 {%0, %1}, %2;" : "=f"(lo), "=f"(hi) : "l"(v));
    return make_float2(lo, hi);
}

// ---------------- graph preprocessing ----------------------------------------

__global__ void zero_deg_k() {
    int i0 = blockIdx.x * blockDim.x + threadIdx.x;
    int stride = gridDim.x * blockDim.x;
    for (int i = i0; i < NN; i += stride) { g_odeg[i] = 0; g_ideg[i] = 0; }
}

__global__ void degree_k(const int* __restrict__ src, const int* __restrict__ dst) {
    int i0 = blockIdx.x * blockDim.x + threadIdx.x;
    int stride = gridDim.x * blockDim.x;
    for (int i = i0; i < NE; i += stride) {
        atomicAdd(&g_odeg[src[i]], 1);
        atomicAdd(&g_ideg[dst[i]], 1);
    }
}

// norms (grid-stride) + per-chunk partial degree sums (first SCAN_T threads)
__global__ void norm_partial_k() {
    int gid = blockIdx.x * blockDim.x + threadIdx.x;
    int stride = gridDim.x * blockDim.x;
    for (int i = gid; i < NN; i += stride) {
        int od = g_odeg[i]; if (od < 1) od = 1;
        int id = g_ideg[i]; if (id < 1) id = 1;
        g_nout[i] = rsqrtf((float)od);
        g_nin[i]  = rsqrtf((float)id);
    }
    if (gid < SCAN_T) {
        int begin = gid * CHUNK;
        int endi  = begin + CHUNK; if (endi > NN) endi = NN;
        int sum = 0;
        if (begin < NN) {
            const int4* p = reinterpret_cast<const int4*>(g_ideg);
            #pragma unroll 13
            for (int i = begin / 4; i < endi / 4; i++) {
                int4 v = p[i];
                sum += v.x + v.y + v.z + v.w;
            }
        }
        g_part[gid] = sum;
    }
}

__global__ void __launch_bounds__(SCAN_T, 1) scanpart_k() {
    __shared__ int part[SCAN_T];
    int t = threadIdx.x;
    part[t] = g_part[t];
    __syncthreads();
    for (int d = 1; d < SCAN_T; d <<= 1) {
        int v = (t >= d) ? part[t - d] : 0;
        __syncthreads();
        part[t] += v;
        __syncthreads();
    }
    g_pref[t] = (t == 0) ? 0 : part[t - 1];   // exclusive
}

__global__ void offsets_k() {
    int t = blockIdx.x * blockDim.x + threadIdx.x;
    if (t >= SCAN_T) return;
    int begin = t * CHUNK;
    int endi  = begin + CHUNK; if (endi > NN) endi = NN;
    int running = g_pref[t];
    for (int i = begin; i < endi; i++) {
        g_off[i] = running;
        g_cur[i] = running;
        running += g_ideg[i];
    }
    if (t == SCAN_T - 1) g_off[NN] = NE;
}

__global__ void scatter_k(const int* __restrict__ src, const int* __restrict__ dst) {
    int i0 = blockIdx.x * blockDim.x + threadIdx.x;
    int stride = gridDim.x * blockDim.x;
    for (int i = i0; i < NE; i += stride) {
        int d = dst[i];
        int pos = atomicAdd(&g_cur[d], 1);
        g_bucket[pos] = src[i];
    }
}

// ---------------- layer-1 SpMM as gather --------------------------------------
__global__ void spmm1g_k(const float* __restrict__ h) {
    unsigned w = (blockIdx.x * blockDim.x + threadIdx.x) >> 5;
    if (w >= NN) return;
    int lane = threadIdx.x & 31;
    int beg = g_off[w];
    int end = g_off[w + 1];
    const float4* h4 = reinterpret_cast<const float4*>(h);

    float4 acc = make_float4(0.f, 0.f, 0.f, 0.f);
    int e = beg;
    for (; e + 1 < end; e += 2) {
        int s0 = __ldg(&g_bucket[e]);
        int s1 = __ldg(&g_bucket[e + 1]);
        float n0 = g_nout[s0];
        float n1 = g_nout[s1];
        float4 v0 = h4[(size_t)s0 * 32 + lane];
        float4 v1 = h4[(size_t)s1 * 32 + lane];
        acc.x = fmaf(v0.x, n0, acc.x); acc.y = fmaf(v0.y, n0, acc.y);
        acc.z = fmaf(v0.z, n0, acc.z); acc.w = fmaf(v0.w, n0, acc.w);
        acc.x = fmaf(v1.x, n1, acc.x); acc.y = fmaf(v1.y, n1, acc.y);
        acc.z = fmaf(v1.z, n1, acc.z); acc.w = fmaf(v1.w, n1, acc.w);
    }
    if (e < end) {
        int s0 = __ldg(&g_bucket[e]);
        float n0 = g_nout[s0];
        float4 v0 = h4[(size_t)s0 * 32 + lane];
        acc.x = fmaf(v0.x, n0, acc.x); acc.y = fmaf(v0.y, n0, acc.y);
        acc.z = fmaf(v0.z, n0, acc.z); acc.w = fmaf(v0.w, n0, acc.w);
    }
    float ni = g_nin[w];
    acc.x *= ni; acc.y *= ni; acc.z *= ni; acc.w *= ni;
    reinterpret_cast<float4*>(g_ax)[(size_t)w * 32 + lane] = acc;
}

// ---------------- layer-2 SpMM as gather + fused epilogue ---------------------
__global__ void spmm2g_k(const float* __restrict__ b2, float* __restrict__ out) {
    unsigned w = (blockIdx.x * blockDim.x + threadIdx.x) >> 5;
    if (w >= NN) return;
    int lane = threadIdx.x & 31;
    int beg = g_off[w];
    int end = g_off[w + 1];
    const float2* y2 = reinterpret_cast<const float2*>(g_y2);

    float2 acc = make_float2(0.f, 0.f);
    int e = beg;
    for (; e + 1 < end; e += 2) {
        int s0 = __ldg(&g_bucket[e]);
        int s1 = __ldg(&g_bucket[e + 1]);
        float2 v0 = y2[(size_t)s0 * 32 + lane];
        float2 v1 = y2[(size_t)s1 * 32 + lane];
        acc.x += v0.x + v1.x;
        acc.y += v0.y + v1.y;
    }
    if (e < end) {
        int s0 = __ldg(&g_bucket[e]);
        float2 v0 = y2[(size_t)s0 * 32 + lane];
        acc.x += v0.x;
        acc.y += v0.y;
    }
    float ni = g_nin[w];
    float2 bb = reinterpret_cast<const float2*>(b2)[lane];
    float2 o;
    o.x = fmaxf(fmaf(acc.x, ni, bb.x), 0.f);
    o.y = fmaxf(fmaf(acc.y, ni, bb.y), 0.f);
    reinterpret_cast<float2*>(out)[(size_t)w * 32 + lane] = o;
}

// ---------------- fused double-GEMM (f32x2, 128-row tiles) --------------------
// Per 128-row tile:
//   A  = g_ax[rows]                          (SMEM, transposed: sA[k][m])
//   H1 = relu(A @ W1 + b1) * norm_out[row]   (overwrites sA as H^T[c][m])
//   y2[rows] = H1 @ W2
// SMEM: W1 64KB + W2 32KB + A/H 64KB + b1 = ~160.5KB -> 1 CTA/SM.
static constexpr int FUSED_SMEM =
    (128 * 128 + 128 * 64 + 128 * 128 + 128) * (int)sizeof(float);

__global__ void __launch_bounds__(256, 1)
fused_mlp_k(const float* __restrict__ W1, const float* __restrict__ b1,
            const float* __restrict__ W2) {
    extern __shared__ float sm[];
    float* sW1 = sm;                        // [128][128] k-major
    float* sW2 = sm + 16384;                // [128][64]
    float* sA  = sm + 16384 + 8192;         // [128][128]  A^T: sA[k][m]; later H^T[c][m]
    float* sb  = sm + 16384 + 8192 + 16384; // [128]
    const int tid = threadIdx.x;

    // stage weights
    {
        const float4* w1 = reinterpret_cast<const float4*>(W1);
        float4* d1 = reinterpret_cast<float4*>(sW1);
        #pragma unroll 4
        for (int i = tid; i < 4096; i += 256) d1[i] = w1[i];
        const float4* w2 = reinterpret_cast<const float4*>(W2);
        float4* d2 = reinterpret_cast<float4*>(sW2);
        #pragma unroll 2
        for (int i = tid; i < 2048; i += 256) d2[i] = w2[i];
        if (tid < 128) sb[tid] = b1[tid];
    }

    const int row0 = blockIdx.x * 128;

    // stage A tile transposed: thread handles row m = tid>>1, k-half q = tid&1
    {
        int m = tid >> 1;
        int q = tid & 1;
        int r = row0 + m;
        bool ok = (r < NN);
        const float4* ar =
            reinterpret_cast<const float4*>(g_ax + (size_t)(ok ? r : 0) * 128);
        #pragma unroll
        for (int kk = 0; kk < 16; kk++) {
            int k4 = q * 16 + kk;                  // float4 index 0..31
            float4 v = ok ? ar[k4] : make_float4(0.f, 0.f, 0.f, 0.f);
            sA[(k4 * 4 + 0) * 128 + m] = v.x;
            sA[(k4 * 4 + 1) * 128 + m] = v.y;
            sA[(k4 * 4 + 2) * 128 + m] = v.z;
            sA[(k4 * 4 + 3) * 128 + m] = v.w;
        }
    }
    __syncthreads();

    const int tm = tid & 15;   // row group: rows tm*8 .. tm*8+7 (4 packed pairs)
    const int tn = tid >> 4;   // col group: cols tn*8 .. tn*8+7

    // GEMM1: H1(128x128) = A @ W1, 8x8 per thread, f32x2 row-pair accumulators
    float hv[8][8];            // unpacked H values [row][col] for this thread
    {
        unsigned long long acc[4][8];  // [rowpair][col]
        #pragma unroll
        for (int p = 0; p < 4; p++)
            #pragma unroll
            for (int i = 0; i < 8; i++) acc[p][i] = 0ull;

        #pragma unroll 4
        for (int k = 0; k < 128; k++) {
            // A rows packed in pairs straight from sA[k][m]
            ulonglong2 aA = *reinterpret_cast<const ulonglong2*>(sA + k * 128 + tm * 8);
            ulonglong2 aB = *reinterpret_cast<const ulonglong2*>(sA + k * 128 + tm * 8 + 4);
            float4 b0 = *reinterpret_cast<const float4*>(sW1 + k * 128 + tn * 8);
            float4 b1v = *reinterpret_cast<const float4*>(sW1 + k * 128 + tn * 8 + 4);
            unsigned long long ap[4] = {aA.x, aA.y, aB.x, aB.y};
            unsigned long long bd[8] = {pack2(b0.x),  pack2(b0.y),  pack2(b0.z),  pack2(b0.w),
                                        pack2(b1v.x), pack2(b1v.y), pack2(b1v.z), pack2(b1v.w)};
            #pragma unroll
            for (int p = 0; p < 4; p++)
                #pragma unroll
                for (int i = 0; i < 8; i++)
                    fma2(acc[p][i], ap[p], bd[i]);
        }

        // epilogue: +b1, relu, *norm_out  (into registers)
        float no[8];
        #pragma unroll
        for (int j = 0; j < 8; j++) {
            int r = row0 + tm * 8 + j;
            no[j] = (r < NN) ? g_nout[r] : 0.f;
        }
        #pragma unroll
        for (int i = 0; i < 8; i++) {
            float bb = sb[tn * 8 + i];
            #pragma unroll
            for (int p = 0; p < 4; p++) {
                float2 v = unpk(acc[p][i]);
                hv[2 * p + 0][i] = fmaxf(v.x + bb, 0.f) * no[2 * p + 0];
                hv[2 * p + 1][i] = fmaxf(v.y + bb, 0.f) * no[2 * p + 1];
            }
        }
    }

    __syncthreads();   // all GEMM1 reads of sA complete

    // store H^T into sA region: sH[c][m]
    #pragma unroll
    for (int i = 0; i < 8; i++) {
        int c = tn * 8 + i;
        float4 v0 = make_float4(hv[0][i], hv[1][i], hv[2][i], hv[3][i]);
        float4 v1 = make_float4(hv[4][i], hv[5][i], hv[6][i], hv[7][i]);
        *reinterpret_cast<float4*>(sA + c * 128 + tm * 8)     = v0;
        *reinterpret_cast<float4*>(sA + c * 128 + tm * 8 + 4) = v1;
    }
    __syncthreads();

    // GEMM2: y2(128x64) = H1 @ W2, 8 rows x 4 cols per thread
    {
        unsigned long long acc[4][4];  // [rowpair][col]
        #pragma unroll
        for (int p = 0; p < 4; p++)
            #pragma unroll
            for (int i = 0; i < 4; i++) acc[p][i] = 0ull;

        #pragma unroll 4
        for (int k = 0; k < 128; k++) {
            ulonglong2 aA = *reinterpret_cast<const ulonglong2*>(sA + k * 128 + tm * 8);
            ulonglong2 aB = *reinterpret_cast<const ulonglong2*>(sA + k * 128 + tm * 8 + 4);
            float4 b = *reinterpret_cast<const float4*>(sW2 + k * 64 + tn * 4);
            unsigned long long ap[4] = {aA.x, aA.y, aB.x, aB.y};
            unsigned long long bd[4] = {pack2(b.x), pack2(b.y), pack2(b.z), pack2(b.w)};
            #pragma unroll
            for (int p = 0; p < 4; p++)
                #pragma unroll
                for (int i = 0; i < 4; i++)
                    fma2(acc[p][i], ap[p], bd[i]);
        }

        #pragma unroll
        for (int p = 0; p < 4; p++) {
            float2 c0 = unpk(acc[p][0]);
            float2 c1 = unpk(acc[p][1]);
            float2 c2 = unpk(acc[p][2]);
            float2 c3 = unpk(acc[p][3]);
            int r0r = row0 + tm * 8 + 2 * p;
            if (r0r < NN) {
                float4 o = make_float4(c0.x, c1.x, c2.x, c3.x);
                *reinterpret_cast<float4*>(g_y2 + (size_t)r0r * 64 + tn * 4) = o;
            }
            if (r0r + 1 < NN) {
                float4 o = make_float4(c0.y, c1.y, c2.y, c3.y);
                *reinterpret_cast<float4*>(g_y2 + (size_t)(r0r + 1) * 64 + tn * 4) = o;
            }
        }
    }
}

// ---------------- launch ------------------------------------------------------

extern "C" void kernel_launch(void* const* d_in, const int* in_sizes, int n_in,
                              void* d_out, int out_size) {
    const float* h  = (const float*)d_in[0];
    const float* W1 = (const float*)d_in[1];
    const float* b1 = (const float*)d_in[2];
    const float* W2 = (const float*)d_in[3];
    const float* b2 = (const float*)d_in[4];
    const int*   src = (const int*)d_in[5];
    const int*   dst = (const int*)d_in[6];
    float* out = (float*)d_out;
    (void)in_sizes; (void)n_in; (void)out_size;

    cudaFuncSetAttribute(fused_mlp_k,
                         cudaFuncAttributeMaxDynamicSharedMemorySize, FUSED_SMEM);

    zero_deg_k<<<98, 512>>>();
    degree_k<<<1024, 256>>>(src, dst);
    norm_partial_k<<<98, 512>>>();     // norms + scan phase A fused
    scanpart_k<<<1, SCAN_T>>>();
    offsets_k<<<8, 128>>>();
    scatter_k<<<1024, 256>>>(src, dst);
    spmm1g_k<<<(NN * 32 + 255) / 256, 256>>>(h);            // 1 warp/node
    fused_mlp_k<<<(NN + 127) / 128, 256, FUSED_SMEM>>>(W1, b1, W2);
    spmm2g_k<<<(NN * 32 + 255) / 256, 256>>>(b2, out);      // 1 warp/node
}

// round 9
// speedup vs baseline: 1.4788x; 1.0101x over previous
#include <cuda_runtime.h>
#include <cuda_fp16.h>

// Problem constants (fixed by the dataset)
static constexpr int NN = 50000;   // nodes
static constexpr int NE = 800000;  // edges
// features: 128 -> 128 (hidden) -> 64 (out)

// scan decomposition (CHUNK divisible by 4 for int4 loads)
static constexpr int SCAN_T = 1024;
static constexpr int CHUNK  = 52;          // 1024*52 = 53248 >= NN

// ---------------- scratch (__device__ globals; no allocs allowed) ------------
__device__ float  g_ax [(size_t)NN * 128]; // nin-scaled layer1 aggregate (GEMM input A)
__device__ float  g_y2 [(size_t)NN * 64];  // (relu(h1)*nout) @ W2
__device__ __half g_hx [(size_t)NN * 128]; // h * nout, fp16 (layer1 gather source)
__device__ int    g_odeg[NN];
__device__ int    g_ideg[NN];
__device__ float  g_nout[NN];
__device__ float  g_nin [NN];
__device__ int    g_off [NN + 1];          // CSR offsets (by dst)
__device__ int    g_cur [NN];              // scatter cursors
__device__ int    g_bucket[NE];            // src ids grouped by dst
__device__ int    g_part[SCAN_T];          // per-chunk partial sums
__device__ int    g_pref[SCAN_T];          // exclusive prefix of partials

// ---------------- packed f32x2 helpers (PTX-only) -----------------------------
__device__ __forceinline__ void fma2(unsigned long long& d,
                                     unsigned long long a,
                                     unsigned long long b) {
    asm("fma.rn.f32x2 %0, %1, %2, %0;" : "+l"(d) : "l"(a), "l"(b));
}
__device__ __forceinline__ unsigned long long pack2(float x) {
    unsigned long long r;
    asm("mov.b64 %0, {%1, %1};" : "=l"(r) : "f"(x));
    return r;
}
__device__ __forceinline__ float2 unpk(unsigned long long v) {
    float lo, hi;
    asm("mov.b64 {%0, %1}, %2;" : "=f"(lo), "=f"(hi) : "l"(v));
    return make_float2(lo, hi);
}

// ---------------- graph preprocessing ----------------------------------------

__global__ void zero_deg_k() {
    int i0 = blockIdx.x * blockDim.x + threadIdx.x;
    int stride = gridDim.x * blockDim.x;
    for (int i = i0; i < NN; i += stride) { g_odeg[i] = 0; g_ideg[i] = 0; }
}

__global__ void degree_k(const int* __restrict__ src, const int* __restrict__ dst) {
    int i0 = blockIdx.x * blockDim.x + threadIdx.x;
    int stride = gridDim.x * blockDim.x;
    for (int i = i0; i < NE; i += stride) {
        atomicAdd(&g_odeg[src[i]], 1);
        atomicAdd(&g_ideg[dst[i]], 1);
    }
}

// norms (grid-stride) + per-chunk partial degree sums (first SCAN_T threads)
__global__ void norm_partial_k() {
    int gid = blockIdx.x * blockDim.x + threadIdx.x;
    int stride = gridDim.x * blockDim.x;
    for (int i = gid; i < NN; i += stride) {
        int od = g_odeg[i]; if (od < 1) od = 1;
        int id = g_ideg[i]; if (id < 1) id = 1;
        g_nout[i] = rsqrtf((float)od);
        g_nin[i]  = rsqrtf((float)id);
    }
    if (gid < SCAN_T) {
        int begin = gid * CHUNK;
        int endi  = begin + CHUNK; if (endi > NN) endi = NN;
        int sum = 0;
        if (begin < NN) {
            const int4* p = reinterpret_cast<const int4*>(g_ideg);
            #pragma unroll 13
            for (int i = begin / 4; i < endi / 4; i++) {
                int4 v = p[i];
                sum += v.x + v.y + v.z + v.w;
            }
        }
        g_part[gid] = sum;
    }
}

__global__ void __launch_bounds__(SCAN_T, 1) scanpart_k() {
    __shared__ int part[SCAN_T];
    int t = threadIdx.x;
    part[t] = g_part[t];
    __syncthreads();
    for (int d = 1; d < SCAN_T; d <<= 1) {
        int v = (t >= d) ? part[t - d] : 0;
        __syncthreads();
        part[t] += v;
        __syncthreads();
    }
    g_pref[t] = (t == 0) ? 0 : part[t - 1];   // exclusive
}

__global__ void offsets_k() {
    int t = blockIdx.x * blockDim.x + threadIdx.x;
    if (t >= SCAN_T) return;
    int begin = t * CHUNK;
    int endi  = begin + CHUNK; if (endi > NN) endi = NN;
    int running = g_pref[t];
    for (int i = begin; i < endi; i++) {
        g_off[i] = running;
        g_cur[i] = running;
        running += g_ideg[i];
    }
    if (t == SCAN_T - 1) g_off[NN] = NE;
}

__global__ void scatter_k(const int* __restrict__ src, const int* __restrict__ dst) {
    int i0 = blockIdx.x * blockDim.x + threadIdx.x;
    int stride = gridDim.x * blockDim.x;
    for (int i = i0; i < NE; i += stride) {
        int d = dst[i];
        int pos = atomicAdd(&g_cur[d], 1);
        g_bucket[pos] = src[i];
    }
}

// ---------------- fp16 pre-scaled features ------------------------------------
// g_hx[n][f] = half(h[n][f] * nout[n]); folds the per-edge src scaling in.
__global__ void h2half_k(const float* __restrict__ h) {
    int i0 = blockIdx.x * blockDim.x + threadIdx.x;
    int stride = gridDim.x * blockDim.x;
    const float4* h4 = reinterpret_cast<const float4*>(h);
    uint2* o = reinterpret_cast<uint2*>(g_hx);
    for (int i = i0; i < NN * 32; i += stride) {   // 32 float4 per row
        int row = i >> 5;
        float s = g_nout[row];
        float4 v = h4[i];
        __half2 a = __floats2half2_rn(v.x * s, v.y * s);
        __half2 b = __floats2half2_rn(v.z * s, v.w * s);
        uint2 pkd;
        pkd.x = *reinterpret_cast<unsigned*>(&a);
        pkd.y = *reinterpret_cast<unsigned*>(&b);
        o[i] = pkd;
    }
}

// ---------------- layer-1 SpMM as fp16 gather ----------------------------------
// One warp per dst node; lane holds 4 feats (one uint2 = 4 halves per row).
// g_ax[n] = nin[n] * sum_{e in in(n)} g_hx[src_e]
__global__ void spmm1g_k() {
    unsigned w = (blockIdx.x * blockDim.x + threadIdx.x) >> 5;
    if (w >= NN) return;
    int lane = threadIdx.x & 31;
    int beg = g_off[w];
    int end = g_off[w + 1];
    const uint2* hx = reinterpret_cast<const uint2*>(g_hx);

    float4 acc = make_float4(0.f, 0.f, 0.f, 0.f);
    int e = beg;
    for (; e + 1 < end; e += 2) {
        int s0 = __ldg(&g_bucket[e]);
        int s1 = __ldg(&g_bucket[e + 1]);
        uint2 p0 = hx[(size_t)s0 * 32 + lane];
        uint2 p1 = hx[(size_t)s1 * 32 + lane];
        float2 a0 = __half22float2(*reinterpret_cast<__half2*>(&p0.x));
        float2 b0 = __half22float2(*reinterpret_cast<__half2*>(&p0.y));
        float2 a1 = __half22float2(*reinterpret_cast<__half2*>(&p1.x));
        float2 b1 = __half22float2(*reinterpret_cast<__half2*>(&p1.y));
        acc.x += a0.x + a1.x;  acc.y += a0.y + a1.y;
        acc.z += b0.x + b1.x;  acc.w += b0.y + b1.y;
    }
    if (e < end) {
        int s0 = __ldg(&g_bucket[e]);
        uint2 p0 = hx[(size_t)s0 * 32 + lane];
        float2 a0 = __half22float2(*reinterpret_cast<__half2*>(&p0.x));
        float2 b0 = __half22float2(*reinterpret_cast<__half2*>(&p0.y));
        acc.x += a0.x;  acc.y += a0.y;
        acc.z += b0.x;  acc.w += b0.y;
    }
    float ni = g_nin[w];
    acc.x *= ni; acc.y *= ni; acc.z *= ni; acc.w *= ni;
    reinterpret_cast<float4*>(g_ax)[(size_t)w * 32 + lane] = acc;
}

// ---------------- layer-2 SpMM as gather + fused epilogue ---------------------
__global__ void spmm2g_k(const float* __restrict__ b2, float* __restrict__ out) {
    unsigned w = (blockIdx.x * blockDim.x + threadIdx.x) >> 5;
    if (w >= NN) return;
    int lane = threadIdx.x & 31;
    int beg = g_off[w];
    int end = g_off[w + 1];
    const float2* y2 = reinterpret_cast<const float2*>(g_y2);

    float2 acc = make_float2(0.f, 0.f);
    int e = beg;
    for (; e + 1 < end; e += 2) {
        int s0 = __ldg(&g_bucket[e]);
        int s1 = __ldg(&g_bucket[e + 1]);
        float2 v0 = y2[(size_t)s0 * 32 + lane];
        float2 v1 = y2[(size_t)s1 * 32 + lane];
        acc.x += v0.x + v1.x;
        acc.y += v0.y + v1.y;
    }
    if (e < end) {
        int s0 = __ldg(&g_bucket[e]);
        float2 v0 = y2[(size_t)s0 * 32 + lane];
        acc.x += v0.x;
        acc.y += v0.y;
    }
    float ni = g_nin[w];
    float2 bb = reinterpret_cast<const float2*>(b2)[lane];
    float2 o;
    o.x = fmaxf(fmaf(acc.x, ni, bb.x), 0.f);
    o.y = fmaxf(fmaf(acc.y, ni, bb.y), 0.f);
    reinterpret_cast<float2*>(out)[(size_t)w * 32 + lane] = o;
}

// ---------------- fused double-GEMM (f32x2, 128-row tiles) --------------------
static constexpr int FUSED_SMEM =
    (128 * 128 + 128 * 64 + 128 * 128 + 128) * (int)sizeof(float);

__global__ void __launch_bounds__(256, 1)
fused_mlp_k(const float* __restrict__ W1, const float* __restrict__ b1,
            const float* __restrict__ W2) {
    extern __shared__ float sm[];
    float* sW1 = sm;                        // [128][128] k-major
    float* sW2 = sm + 16384;                // [128][64]
    float* sA  = sm + 16384 + 8192;         // [128][128]  A^T: sA[k][m]; later H^T[c][m]
    float* sb  = sm + 16384 + 8192 + 16384; // [128]
    const int tid = threadIdx.x;

    {
        const float4* w1 = reinterpret_cast<const float4*>(W1);
        float4* d1 = reinterpret_cast<float4*>(sW1);
        #pragma unroll 4
        for (int i = tid; i < 4096; i += 256) d1[i] = w1[i];
        const float4* w2 = reinterpret_cast<const float4*>(W2);
        float4* d2 = reinterpret_cast<float4*>(sW2);
        #pragma unroll 2
        for (int i = tid; i < 2048; i += 256) d2[i] = w2[i];
        if (tid < 128) sb[tid] = b1[tid];
    }

    const int row0 = blockIdx.x * 128;

    {
        int m = tid >> 1;
        int q = tid & 1;
        int r = row0 + m;
        bool ok = (r < NN);
        const float4* ar =
            reinterpret_cast<const float4*>(g_ax + (size_t)(ok ? r : 0) * 128);
        #pragma unroll
        for (int kk = 0; kk < 16; kk++) {
            int k4 = q * 16 + kk;
            float4 v = ok ? ar[k4] : make_float4(0.f, 0.f, 0.f, 0.f);
            sA[(k4 * 4 + 0) * 128 + m] = v.x;
            sA[(k4 * 4 + 1) * 128 + m] = v.y;
            sA[(k4 * 4 + 2) * 128 + m] = v.z;
            sA[(k4 * 4 + 3) * 128 + m] = v.w;
        }
    }
    __syncthreads();

    const int tm = tid & 15;
    const int tn = tid >> 4;

    float hv[8][8];
    {
        unsigned long long acc[4][8];
        #pragma unroll
        for (int p = 0; p < 4; p++)
            #pragma unroll
            for (int i = 0; i < 8; i++) acc[p][i] = 0ull;

        #pragma unroll 4
        for (int k = 0; k < 128; k++) {
            ulonglong2 aA = *reinterpret_cast<const ulonglong2*>(sA + k * 128 + tm * 8);
            ulonglong2 aB = *reinterpret_cast<const ulonglong2*>(sA + k * 128 + tm * 8 + 4);
            float4 b0 = *reinterpret_cast<const float4*>(sW1 + k * 128 + tn * 8);
            float4 b1v = *reinterpret_cast<const float4*>(sW1 + k * 128 + tn * 8 + 4);
            unsigned long long ap[4] = {aA.x, aA.y, aB.x, aB.y};
            unsigned long long bd[8] = {pack2(b0.x),  pack2(b0.y),  pack2(b0.z),  pack2(b0.w),
                                        pack2(b1v.x), pack2(b1v.y), pack2(b1v.z), pack2(b1v.w)};
            #pragma unroll
            for (int p = 0; p < 4; p++)
                #pragma unroll
                for (int i = 0; i < 8; i++)
                    fma2(acc[p][i], ap[p], bd[i]);
        }

        float no[8];
        #pragma unroll
        for (int j = 0; j < 8; j++) {
            int r = row0 + tm * 8 + j;
            no[j] = (r < NN) ? g_nout[r] : 0.f;
        }
        #pragma unroll
        for (int i = 0; i < 8; i++) {
            float bb = sb[tn * 8 + i];
            #pragma unroll
            for (int p = 0; p < 4; p++) {
                float2 v = unpk(acc[p][i]);
                hv[2 * p + 0][i] = fmaxf(v.x + bb, 0.f) * no[2 * p + 0];
                hv[2 * p + 1][i] = fmaxf(v.y + bb, 0.f) * no[2 * p + 1];
            }
        }
    }

    __syncthreads();

    #pragma unroll
    for (int i = 0; i < 8; i++) {
        int c = tn * 8 + i;
        float4 v0 = make_float4(hv[0][i], hv[1][i], hv[2][i], hv[3][i]);
        float4 v1 = make_float4(hv[4][i], hv[5][i], hv[6][i], hv[7][i]);
        *reinterpret_cast<float4*>(sA + c * 128 + tm * 8)     = v0;
        *reinterpret_cast<float4*>(sA + c * 128 + tm * 8 + 4) = v1;
    }
    __syncthreads();

    {
        unsigned long long acc[4][4];
        #pragma unroll
        for (int p = 0; p < 4; p++)
            #pragma unroll
            for (int i = 0; i < 4; i++) acc[p][i] = 0ull;

        #pragma unroll 4
        for (int k = 0; k < 128; k++) {
            ulonglong2 aA = *reinterpret_cast<const ulonglong2*>(sA + k * 128 + tm * 8);
            ulonglong2 aB = *reinterpret_cast<const ulonglong2*>(sA + k * 128 + tm * 8 + 4);
            float4 b = *reinterpret_cast<const float4*>(sW2 + k * 64 + tn * 4);
            unsigned long long ap[4] = {aA.x, aA.y, aB.x, aB.y};
            unsigned long long bd[4] = {pack2(b.x), pack2(b.y), pack2(b.z), pack2(b.w)};
            #pragma unroll
            for (int p = 0; p < 4; p++)
                #pragma unroll
                for (int i = 0; i < 4; i++)
                    fma2(acc[p][i], ap[p], bd[i]);
        }

        #pragma unroll
        for (int p = 0; p < 4; p++) {
            float2 c0 = unpk(acc[p][0]);
            float2 c1 = unpk(acc[p][1]);
            float2 c2 = unpk(acc[p][2]);
            float2 c3 = unpk(acc[p][3]);
            int r0r = row0 + tm * 8 + 2 * p;
            if (r0r < NN) {
                float4 o = make_float4(c0.x, c1.x, c2.x, c3.x);
                *reinterpret_cast<float4*>(g_y2 + (size_t)r0r * 64 + tn * 4) = o;
            }
            if (r0r + 1 < NN) {
                float4 o = make_float4(c0.y, c1.y, c2.y, c3.y);
                *reinterpret_cast<float4*>(g_y2 + (size_t)(r0r + 1) * 64 + tn * 4) = o;
            }
        }
    }
}

// ---------------- launch ------------------------------------------------------

extern "C" void kernel_launch(void* const* d_in, const int* in_sizes, int n_in,
                              void* d_out, int out_size) {
    const float* h  = (const float*)d_in[0];
    const float* W1 = (const float*)d_in[1];
    const float* b1 = (const float*)d_in[2];
    const float* W2 = (const float*)d_in[3];
    const float* b2 = (const float*)d_in[4];
    const int*   src = (const int*)d_in[5];
    const int*   dst = (const int*)d_in[6];
    float* out = (float*)d_out;
    (void)in_sizes; (void)n_in; (void)out_size;

    cudaFuncSetAttribute(fused_mlp_k,
                         cudaFuncAttributeMaxDynamicSharedMemorySize, FUSED_SMEM);

    zero_deg_k<<<98, 512>>>();
    degree_k<<<1024, 256>>>(src, dst);
    norm_partial_k<<<98, 512>>>();     // norms + scan phase A fused
    scanpart_k<<<1, SCAN_T>>>();
    h2half_k<<<1024, 256>>>(h);        // fp16 pre-scaled features
    offsets_k<<<8, 128>>>();
    scatter_k<<<1024, 256>>>(src, dst);
    spmm1g_k<<<(NN * 32 + 255) / 256, 256>>>();             // 1 warp/node, fp16 gather
    fused_mlp_k<<<(NN + 127) / 128, 256, FUSED_SMEM>>>(W1, b1, W2);
    spmm2g_k<<<(NN * 32 + 255) / 256, 256>>>(b2, out);      // 1 warp/node
}